// round 9
// baseline (speedup 1.0000x reference)
#include <cuda_runtime.h>
#include <cuda_fp16.h>
#include <math.h>
#include <stdint.h>

#define B_   64
#define L_   1024
#define ENC_ 2048
#define DEC_ 512
#define ATT_ 512
#define BL_  (B_ * L_)

// ---------------------------------------------------------------------------
// Device scratch
// ---------------------------------------------------------------------------
__device__ float g_H[B_ * ATT_];                          // proj_h + b2 + b1
// W1 fp16, layout [c=k/64][n 512][k 64]
__device__ __align__(128) __half g_B16[ENC_ * ATT_];
// F fp16, layout [mb=row/128][c=k/64][row 128][k 64]
__device__ __align__(128) __half g_F16[(size_t)BL_ * ENC_];
__device__ float g_scorep[4 * BL_];                       // per-N-chunk score partials
__device__ float g_ctxp[8 * B_ * ENC_];                   // context partials

// ---------------------------------------------------------------------------
// Helpers
// ---------------------------------------------------------------------------
__device__ __forceinline__ uint32_t smem_u32(const void* p) {
    uint32_t a;
    asm("{ .reg .u64 t; cvta.to.shared.u64 t, %1; cvt.u32.u64 %0, t; }" : "=r"(a) : "l"(p));
    return a;
}
__device__ __forceinline__ void cp16(uint32_t dst, const void* src) {
    asm volatile("cp.async.cg.shared.global [%0], [%1], 16;" :: "r"(dst), "l"(src));
}
__device__ __forceinline__ void cp_commit() {
    asm volatile("cp.async.commit_group;" ::: "memory");
}
__device__ __forceinline__ void cp_wait1() {
    asm volatile("cp.async.wait_group 1;" ::: "memory");
}
__device__ __forceinline__ void ldsm_x4(uint32_t* r, uint32_t addr) {
    asm volatile("ldmatrix.sync.aligned.m8n8.x4.shared.b16 {%0,%1,%2,%3}, [%4];"
                 : "=r"(r[0]), "=r"(r[1]), "=r"(r[2]), "=r"(r[3]) : "r"(addr));
}
__device__ __forceinline__ void mma_f16(float* d, const uint32_t* a, const uint32_t* b) {
    asm volatile(
        "mma.sync.aligned.m16n8k16.row.col.f32.f16.f16.f32 "
        "{%0,%1,%2,%3}, {%4,%5,%6,%7}, {%8,%9}, {%0,%1,%2,%3};"
        : "+f"(d[0]), "+f"(d[1]), "+f"(d[2]), "+f"(d[3])
        : "r"(a[0]), "r"(a[1]), "r"(a[2]), "r"(a[3]), "r"(b[0]), "r"(b[1]));
}
__device__ __forceinline__ float fast_tanh(float x) {
    float e = __expf(2.f * x);
    return __fdividef(e - 1.f, e + 1.f);
}

// ---------------------------------------------------------------------------
// Kernel A: H = hidden @ W2 + b2 + b1
// ---------------------------------------------------------------------------
__global__ void proj_h_kernel(const float* __restrict__ hidden,
                              const float* __restrict__ W2,
                              const float* __restrict__ b2,
                              const float* __restrict__ b1) {
    __shared__ float hs[DEC_];
    int b = blockIdx.x, a = threadIdx.x;
    hs[a] = hidden[b * DEC_ + a];
    __syncthreads();
    float acc = 0.f;
#pragma unroll 8
    for (int d = 0; d < DEC_; ++d) acc += hs[d] * W2[d * ATT_ + a];
    g_H[b * ATT_ + a] = acc + b2[a] + b1[a];
}

// ---------------------------------------------------------------------------
// Kernel B1: W1 [ENC, ATT] fp32 -> fp16, layout [c][n][k64]
// ---------------------------------------------------------------------------
__global__ void prep_B_kernel(const float* __restrict__ W1) {
    int idx = blockIdx.x * 256 + threadIdx.x;   // idx = k*512 + n
    if (idx >= ENC_ * ATT_) return;
    int k = idx >> 9, n = idx & 511;
    int c = k >> 6, kk = k & 63;
    g_B16[((size_t)(c * 512 + n) << 6) + kk] = __float2half_rn(W1[idx]);
}

// ---------------------------------------------------------------------------
// Kernel B2: F [BL, ENC] fp32 -> fp16, layout [mb][c][row][k64]
// ---------------------------------------------------------------------------
__global__ void prep_F_kernel(const float* __restrict__ F) {
    size_t f4 = (size_t)blockIdx.x * 256 + threadIdx.x;  // float4 index
    size_t r  = f4 >> 9;            // global row (512 float4 per row)
    int   k   = (int)(f4 & 511) * 4;
    int   mb  = (int)(r >> 7), row = (int)(r & 127);
    int   c   = k >> 6, kk = k & 63;
    float4 f = *(const float4*)(F + (r << 11) + k);
    __half2 h01 = __floats2half2_rn(f.x, f.y);
    __half2 h23 = __floats2half2_rn(f.z, f.w);
    size_t o = (((size_t)(mb * 32 + c) * 128 + row) << 6) + kk;
    *(uint2*)(g_F16 + o) = make_uint2(*(uint32_t*)&h01, *(uint32_t*)&h23);
}

// ---------------------------------------------------------------------------
// Kernel C: fused fp16 mma.sync GEMM + tanh + V-reduction -> score partials
// Grid: (4 nc, 256 m) nc-major. CTA: 256x128, 8 warps (4 wm x 2 wn),
// warp tile 64x64 (halves smem crossbar traffic per FLOP). KC=64, 3 stages.
// ---------------------------------------------------------------------------
static constexpr int PITCH   = 144;             // 128B data + 16B pad
static constexpr int A_TILE  = 256 * PITCH;     // 36864
static constexpr int B_TILE  = 128 * PITCH;     // 18432
static constexpr int STAGE   = A_TILE + B_TILE; // 55296
static constexpr int NSTG    = 3;
static constexpr int OFF_A   = 0;
static constexpr int OFF_B   = A_TILE;
static constexpr int OFF_PART = NSTG * STAGE;          // 165888: 512 floats
static constexpr int OFF_H    = OFF_PART + 2048;
static constexpr int OFF_V    = OFF_H + 512;
static constexpr int SMEM_TOTAL = OFF_V + 512;         // 168960
static constexpr int NCHUNK   = ENC_ / 64;             // 32
static constexpr int A_STRIDE = 128 * 64;              // halves per chunk (per mb)
static constexpr int B_STRIDE = 512 * 64;

__global__ __launch_bounds__(256) void score_mma_kernel(const float* __restrict__ V)
{
    extern __shared__ char smem[];
    const uint32_t sb = smem_u32(smem);
    const int tid  = threadIdx.x;
    const int lane = tid & 31;
    const int wid  = tid >> 5;
    const int wm   = wid & 3;        // warp m: 4 x 64 rows
    const int wn   = wid >> 2;       // warp n: 2 x 64 cols
    const int nc   = blockIdx.x;     // n chunk (128 cols)
    const int by   = blockIdx.y;
    const int m0   = by * 256;
    const int b    = by >> 2;        // 4 CTAs per batch

    float* partS = (float*)(smem + OFF_PART);
    float* Hs    = (float*)(smem + OFF_H);
    float* Vs    = (float*)(smem + OFF_V);
    if (tid < 128) {
        Hs[tid] = g_H[b * ATT_ + nc * 128 + tid];
        Vs[tid] = V[nc * 128 + tid];
    }

    float d[4][8][4];
#pragma unroll
    for (int mt = 0; mt < 4; ++mt)
#pragma unroll
        for (int nt = 0; nt < 8; ++nt)
#pragma unroll
            for (int e = 0; e < 4; ++e) d[mt][nt][e] = 0.f;

    // prefetch state: A 8 units/thread, B 4 units/thread
    uint32_t dstoA[8], dstoB[4];
    const __half* pA[8];
    const __half* pB[4];
#pragma unroll
    for (int e = 0; e < 8; ++e) {
        int j = tid + e * 256, row = j >> 3, q = j & 7;   // row 0..255
        dstoA[e] = (uint32_t)(OFF_A + row * PITCH + q * 16);
        pA[e] = g_F16 + (((size_t)(2 * by + (row >> 7)) * 32 * 128 + (row & 127)) << 6) + q * 8;
    }
#pragma unroll
    for (int e = 0; e < 4; ++e) {
        int j = tid + e * 256, row = j >> 3, q = j & 7;   // row 0..127
        dstoB[e] = (uint32_t)(OFF_B + row * PITCH + q * 16);
        pB[e] = g_B16 + (((size_t)(nc * 128 + row)) << 6) + q * 8;
    }

    // ---- prologue: chunks 0,1 -> stages 0,1 ----
#pragma unroll
    for (int c = 0; c < 2; ++c) {
        const uint32_t stg = sb + c * STAGE;
#pragma unroll
        for (int e = 0; e < 8; ++e) { cp16(stg + dstoA[e], pA[e]); pA[e] += A_STRIDE; }
#pragma unroll
        for (int e = 0; e < 4; ++e) { cp16(stg + dstoB[e], pB[e]); pB[e] += B_STRIDE; }
        cp_commit();
    }

    // hoisted ldsm base offsets (stage-relative)
    uint32_t aoff[4], boff[4];
#pragma unroll
    for (int t = 0; t < 4; ++t)
        aoff[t] = OFF_A + (uint32_t)(wm * 64 + t * 16 + (lane & 15)) * PITCH +
                  (uint32_t)(((lane >> 4) & 1) * 16);
#pragma unroll
    for (int p = 0; p < 4; ++p)
        boff[p] = OFF_B + (uint32_t)(wn * 64 + p * 16 + (lane & 15)) * PITCH +
                  (uint32_t)(((lane >> 4) & 1) * 16);

    int cs = 0, ps = 2;   // compute stage, prefetch stage
#pragma unroll 1
    for (int i = 0; i < NCHUNK; ++i) {
        const uint32_t stg = sb + cs * STAGE;
        if (++cs == NSTG) cs = 0;

        cp_wait1();        // chunk i resident (newest group may still fly)
        __syncthreads();

        if (i + 2 < NCHUNK) {
            const uint32_t nstg = sb + ps * STAGE;
            if (++ps == NSTG) ps = 0;
#pragma unroll
            for (int e = 0; e < 8; ++e) { cp16(nstg + dstoA[e], pA[e]); pA[e] += A_STRIDE; }
#pragma unroll
            for (int e = 0; e < 4; ++e) { cp16(nstg + dstoB[e], pB[e]); pB[e] += B_STRIDE; }
            cp_commit();
        }

        // ---- compute chunk i: 4 k16 slabs ----
#pragma unroll
        for (int kk = 0; kk < 4; ++kk) {
            const uint32_t ko = (uint32_t)(kk * 32);
            uint32_t a[4][4];
#pragma unroll
            for (int t = 0; t < 4; ++t)
                ldsm_x4(a[t], stg + aoff[t] + ko);
            uint32_t bb[8][2];
#pragma unroll
            for (int p = 0; p < 4; ++p) {       // paired ldsm: 2 n-tiles per x4
                uint32_t r[4];
                ldsm_x4(r, stg + boff[p] + ko);
                bb[2 * p][0]     = r[0];
                bb[2 * p + 1][0] = r[1];
                bb[2 * p][1]     = r[2];
                bb[2 * p + 1][1] = r[3];
            }
#pragma unroll
            for (int mt = 0; mt < 4; ++mt)
#pragma unroll
                for (int nt = 0; nt < 8; ++nt)
                    mma_f16(d[mt][nt], a[mt], bb[nt]);
        }
    }

    // ---- epilogue: tanh + V-weighted row reduction over this 128-col chunk ----
#pragma unroll
    for (int mt = 0; mt < 4; ++mt) {
        float s0 = 0.f, s1 = 0.f;
#pragma unroll
        for (int nt = 0; nt < 8; ++nt) {
            int c0 = wn * 64 + nt * 8 + (lane & 3) * 2;
            float h0 = Hs[c0], v0 = Vs[c0];
            float h1 = Hs[c0 + 1], v1 = Vs[c0 + 1];
            s0 += fast_tanh(d[mt][nt][0] + h0) * v0 + fast_tanh(d[mt][nt][1] + h1) * v1;
            s1 += fast_tanh(d[mt][nt][2] + h0) * v0 + fast_tanh(d[mt][nt][3] + h1) * v1;
        }
#pragma unroll
        for (int o = 1; o <= 2; o <<= 1) {
            s0 += __shfl_xor_sync(~0u, s0, o);
            s1 += __shfl_xor_sync(~0u, s1, o);
        }
        if ((lane & 3) == 0) {
            int r = wm * 64 + mt * 16 + (lane >> 2);
            partS[wn * 256 + r]     = s0;
            partS[wn * 256 + r + 8] = s1;
        }
    }
    __syncthreads();
    g_scorep[nc * BL_ + m0 + tid] = partS[tid] + partS[256 + tid];
}

// ---------------------------------------------------------------------------
// Kernel D: combine partials + softmax over L per batch
// ---------------------------------------------------------------------------
__global__ void softmax_kernel(const float* __restrict__ bv, float* __restrict__ w) {
    __shared__ float redm[32];
    __shared__ float reds[32];
    const int b = blockIdx.x, t = threadIdx.x;
    const int idx = b * L_ + t;
    float s = g_scorep[idx] + g_scorep[BL_ + idx] + g_scorep[2 * BL_ + idx] +
              g_scorep[3 * BL_ + idx] + bv[0];
    float m = s;
#pragma unroll
    for (int o = 16; o > 0; o >>= 1) m = fmaxf(m, __shfl_xor_sync(~0u, m, o));
    if ((t & 31) == 0) redm[t >> 5] = m;
    __syncthreads();
    if (t < 32) {
        float v = redm[t];
#pragma unroll
        for (int o = 16; o > 0; o >>= 1) v = fmaxf(v, __shfl_xor_sync(~0u, v, o));
        redm[t] = v;
    }
    __syncthreads();
    m = redm[0];
    const float e = expf(s - m);
    float sum = e;
#pragma unroll
    for (int o = 16; o > 0; o >>= 1) sum += __shfl_xor_sync(~0u, sum, o);
    if ((t & 31) == 0) reds[t >> 5] = sum;
    __syncthreads();
    if (t < 32) {
        float v = reds[t];
#pragma unroll
        for (int o = 16; o > 0; o >>= 1) v += __shfl_xor_sync(~0u, v, o);
        reds[t] = v;
    }
    __syncthreads();
    w[idx] = e / reds[0];
}

// ---------------------------------------------------------------------------
// Kernel E/F: context = sum_l w*F  (fp16 tiled F; 8 L-partials, then reduced)
// ---------------------------------------------------------------------------
__global__ void context_part_kernel(const float* __restrict__ w) {
    __shared__ float ws[128];
    const int b = blockIdx.y, z = blockIdx.z, t = threadIdx.x;
    ws[t] = w[b * L_ + z * 128 + t];
    __syncthreads();
    const int e0 = blockIdx.x * 512 + t * 4;
    const int mb = b * 8 + z;
    const int c  = e0 >> 6, kk = e0 & 63;
    const __half* base = g_F16 + (((size_t)(mb * 32 + c) * 128) << 6) + kk;
    float4 acc = make_float4(0.f, 0.f, 0.f, 0.f);
#pragma unroll 4
    for (int l = 0; l < 128; ++l) {
        uint2 v = *(const uint2*)(base + ((size_t)l << 6));
        float2 f01 = __half22float2(*(const __half2*)&v.x);
        float2 f23 = __half22float2(*(const __half2*)&v.y);
        const float wl = ws[l];
        acc.x += wl * f01.x; acc.y += wl * f01.y;
        acc.z += wl * f23.x; acc.w += wl * f23.y;
    }
    *(float4*)&g_ctxp[(size_t)(z * B_ + b) * ENC_ + e0] = acc;
}

__global__ void context_reduce_kernel(float* __restrict__ ctx) {
    const int i = (blockIdx.x * 256 + threadIdx.x) * 4;
    float4 acc = make_float4(0.f, 0.f, 0.f, 0.f);
#pragma unroll
    for (int p = 0; p < 8; ++p) {
        float4 a = *(const float4*)&g_ctxp[(size_t)p * B_ * ENC_ + i];
        acc.x += a.x; acc.y += a.y; acc.z += a.z; acc.w += a.w;
    }
    *(float4*)&ctx[i] = acc;
}

// ---------------------------------------------------------------------------
// Launch
// ---------------------------------------------------------------------------
extern "C" void kernel_launch(void* const* d_in, const int* in_sizes, int n_in,
                              void* d_out, int out_size) {
    const float* F   = (const float*)d_in[0];
    const float* hid = (const float*)d_in[1];
    const float* W1  = (const float*)d_in[2];
    const float* b1  = (const float*)d_in[3];
    const float* W2  = (const float*)d_in[4];
    const float* b2  = (const float*)d_in[5];
    const float* V   = (const float*)d_in[6];
    const float* bv  = (const float*)d_in[7];

    float* out = (float*)d_out;
    float* ctx = out;
    float* wts = out + B_ * ENC_;

    cudaFuncSetAttribute(score_mma_kernel,
                         cudaFuncAttributeMaxDynamicSharedMemorySize, SMEM_TOTAL);

    proj_h_kernel<<<B_, ATT_>>>(hid, W2, b2, b1);
    prep_B_kernel<<<(ENC_ * ATT_) / 256, 256>>>(W1);
    prep_F_kernel<<<(int)(((size_t)BL_ * ENC_ / 4) / 256), 256>>>(F);
    score_mma_kernel<<<dim3(4, BL_ / 256), 256, SMEM_TOTAL>>>(V);
    softmax_kernel<<<B_, L_>>>(bv, wts);
    context_part_kernel<<<dim3(ENC_ / 512, B_, 8), 128>>>(wts);
    context_reduce_kernel<<<(B_ * ENC_) / 1024, 256>>>(ctx);
}

// round 10
// speedup vs baseline: 1.0123x; 1.0123x over previous
#include <cuda_runtime.h>
#include <cuda_fp16.h>
#include <math.h>
#include <stdint.h>

#define B_   64
#define L_   1024
#define ENC_ 2048
#define DEC_ 512
#define ATT_ 512
#define BL_  (B_ * L_)

// ---------------------------------------------------------------------------
// Device scratch
// ---------------------------------------------------------------------------
__device__ float g_H[B_ * ATT_];                          // proj_h + b2 + b1
// W1 fp16, layout [c=k/64][n 512][k 64]
__device__ __align__(128) __half g_B16[ENC_ * ATT_];
// F fp16, layout [mb=row/128][c=k/64][row 128][k 64]  (written by score_nc0)
__device__ __align__(128) __half g_F16[(size_t)BL_ * ENC_];
__device__ float g_scorep[4 * BL_];                       // per-N-chunk score partials
__device__ float g_ctxp[8 * B_ * ENC_];                   // context partials

// ---------------------------------------------------------------------------
// Helpers
// ---------------------------------------------------------------------------
__device__ __forceinline__ uint32_t smem_u32(const void* p) {
    uint32_t a;
    asm("{ .reg .u64 t; cvta.to.shared.u64 t, %1; cvt.u32.u64 %0, t; }" : "=r"(a) : "l"(p));
    return a;
}
__device__ __forceinline__ void cp16(uint32_t dst, const void* src) {
    asm volatile("cp.async.cg.shared.global [%0], [%1], 16;" :: "r"(dst), "l"(src));
}
__device__ __forceinline__ void cp_commit() {
    asm volatile("cp.async.commit_group;" ::: "memory");
}
__device__ __forceinline__ void cp_wait0() {
    asm volatile("cp.async.wait_group 0;" ::: "memory");
}
__device__ __forceinline__ void cp_wait1() {
    asm volatile("cp.async.wait_group 1;" ::: "memory");
}
__device__ __forceinline__ void ldsm_x4(uint32_t* r, uint32_t addr) {
    asm volatile("ldmatrix.sync.aligned.m8n8.x4.shared.b16 {%0,%1,%2,%3}, [%4];"
                 : "=r"(r[0]), "=r"(r[1]), "=r"(r[2]), "=r"(r[3]) : "r"(addr));
}
__device__ __forceinline__ void mma_f16(float* d, const uint32_t* a, const uint32_t* b) {
    asm volatile(
        "mma.sync.aligned.m16n8k16.row.col.f32.f16.f16.f32 "
        "{%0,%1,%2,%3}, {%4,%5,%6,%7}, {%8,%9}, {%0,%1,%2,%3};"
        : "+f"(d[0]), "+f"(d[1]), "+f"(d[2]), "+f"(d[3])
        : "r"(a[0]), "r"(a[1]), "r"(a[2]), "r"(a[3]), "r"(b[0]), "r"(b[1]));
}
__device__ __forceinline__ float fast_tanh(float x) {
    float e = __expf(2.f * x);
    return __fdividef(e - 1.f, e + 1.f);
}

// ---------------------------------------------------------------------------
// Kernel A: H = hidden @ W2 + b2 + b1
// ---------------------------------------------------------------------------
__global__ void proj_h_kernel(const float* __restrict__ hidden,
                              const float* __restrict__ W2,
                              const float* __restrict__ b2,
                              const float* __restrict__ b1) {
    __shared__ float hs[DEC_];
    int b = blockIdx.x, a = threadIdx.x;
    hs[a] = hidden[b * DEC_ + a];
    __syncthreads();
    float acc = 0.f;
#pragma unroll 8
    for (int d = 0; d < DEC_; ++d) acc += hs[d] * W2[d * ATT_ + a];
    g_H[b * ATT_ + a] = acc + b2[a] + b1[a];
}

// ---------------------------------------------------------------------------
// Kernel B1: W1 [ENC, ATT] fp32 -> fp16, layout [c][n][k64]
// ---------------------------------------------------------------------------
__global__ void prep_B_kernel(const float* __restrict__ W1) {
    int idx = blockIdx.x * 256 + threadIdx.x;   // idx = k*512 + n
    if (idx >= ENC_ * ATT_) return;
    int k = idx >> 9, n = idx & 511;
    int c = k >> 6, kk = k & 63;
    g_B16[((size_t)(c * 512 + n) << 6) + kk] = __float2half_rn(W1[idx]);
}

// ---------------------------------------------------------------------------
// Common tile constants
// ---------------------------------------------------------------------------
static constexpr int PITCH  = 144;            // 128B data + 16B pad
static constexpr int TILE   = 128 * PITCH;    // 18432
static constexpr int NCHUNK = ENC_ / 64;      // 32
static constexpr int A_STRIDE = 128 * 64;     // F16 halves per chunk
static constexpr int B_STRIDE = 512 * 64;

// ===========================================================================
// Kernel C0: nc=0 — reads F fp32, converts, WRITES g_F16, computes chunk 0.
// 2-stage: B via cp.async, A via LDG->regs->cvt->STS (+ STG to g_F16).
// ===========================================================================
static constexpr int N0_STAGE = 2 * TILE;            // A + B = 36864
static constexpr int N0_OFF_A = 0;
static constexpr int N0_OFF_B = TILE;
static constexpr int N0_PART  = 2 * N0_STAGE;        // 73728
static constexpr int N0_H     = N0_PART + 1024;
static constexpr int N0_V     = N0_H + 512;
static constexpr int N0_SMEM  = N0_V + 512;          // 75776

__global__ __launch_bounds__(256, 2) void score_mma_nc0(
    const float* __restrict__ F, const float* __restrict__ V)
{
    extern __shared__ char smem[];
    const uint32_t sb = smem_u32(smem);
    const int tid  = threadIdx.x;
    const int lane = tid & 31;
    const int wid  = tid >> 5;
    const int wm   = wid & 3;
    const int wn   = wid >> 2;
    const int mb   = blockIdx.x;
    const int m0   = mb * 128;
    const int b    = mb >> 3;

    float* partS = (float*)(smem + N0_PART);
    float* Hs    = (float*)(smem + N0_H);
    float* Vs    = (float*)(smem + N0_V);
    if (tid < 128) {
        Hs[tid] = g_H[b * ATT_ + tid];
        Vs[tid] = V[tid];
    }

    float d[2][8][4];
#pragma unroll
    for (int mt = 0; mt < 2; ++mt)
#pragma unroll
        for (int nt = 0; nt < 8; ++nt)
#pragma unroll
            for (int e = 0; e < 4; ++e) d[mt][nt][e] = 0.f;

    // A fp32 load assignment: 2048 float4/chunk -> 8/thread
    // j = tid + e*256; row = j>>4 (0..127), q = j&15 (0..15)
    const int arow = tid >> 1;           // reused pattern: rows 0..127 via j>>4
    (void)arow;
    const float* pF[8];
    const __half* pO[8];                 // gmem F16 output
    uint32_t adst[8];
#pragma unroll
    for (int e = 0; e < 8; ++e) {
        int j = tid + e * 256, row = j >> 4, q = j & 15;
        pF[e]   = F + (size_t)(m0 + row) * ENC_ + q * 4;
        pO[e]   = g_F16 + (((size_t)(mb * 32) * 128 + row) << 6) + q * 4;
        adst[e] = (uint32_t)(N0_OFF_A + row * PITCH + q * 8);
    }
    // B cp assignment (as R8): 4/thread
    uint32_t bdst[4];
    const __half* pB[4];
#pragma unroll
    for (int e = 0; e < 4; ++e) {
        int j = tid + e * 256, row = j >> 3, q = j & 7;
        bdst[e] = (uint32_t)(N0_OFF_B + row * PITCH + q * 16);
        pB[e] = g_B16 + (((size_t)row) << 6) + q * 8;   // nc = 0
    }

    // ---- prologue: chunk 0 ----
    float4 fr[8];
#pragma unroll
    for (int e = 0; e < 8; ++e) { fr[e] = *(const float4*)pF[e]; pF[e] += 64; }
#pragma unroll
    for (int e = 0; e < 4; ++e) { cp16(sb + bdst[e], pB[e]); pB[e] += B_STRIDE; }
    cp_commit();
#pragma unroll
    for (int e = 0; e < 8; ++e) {
        __half2 h01 = __floats2half2_rn(fr[e].x, fr[e].y);
        __half2 h23 = __floats2half2_rn(fr[e].z, fr[e].w);
        uint2 v = make_uint2(*(uint32_t*)&h01, *(uint32_t*)&h23);
        *(uint2*)(smem + adst[e]) = v;
        *(uint2*)pO[e] = v;  pO[e] += A_STRIDE;
    }

    // ldsm offsets
    const uint32_t aoff0 = N0_OFF_A + (uint32_t)(wm * 32 + (lane & 15)) * PITCH +
                           (uint32_t)(((lane >> 4) & 1) * 16);
    const uint32_t aoff1 = aoff0 + 16 * PITCH;
    uint32_t boff[4];
#pragma unroll
    for (int p = 0; p < 4; ++p)
        boff[p] = N0_OFF_B + (uint32_t)(wn * 64 + p * 16 + (lane & 15)) * PITCH +
                  (uint32_t)(((lane >> 4) & 1) * 16);

#pragma unroll 1
    for (int i = 0; i < NCHUNK; ++i) {
        const int s = i & 1;
        const uint32_t stg  = sb + s * N0_STAGE;
        const uint32_t nstg = sb + (s ^ 1) * N0_STAGE;

        // prefetch A(i+1) fp32 into regs
        if (i + 1 < NCHUNK) {
#pragma unroll
            for (int e = 0; e < 8; ++e) { fr[e] = *(const float4*)pF[e]; pF[e] += 64; }
        }

        cp_wait0();
        __syncthreads();   // stage s ready; stage s^1 free (prev compute done)

        if (i + 1 < NCHUNK) {
#pragma unroll
            for (int e = 0; e < 4; ++e) { cp16(nstg + bdst[e], pB[e]); pB[e] += B_STRIDE; }
            cp_commit();
#pragma unroll
            for (int e = 0; e < 8; ++e) {
                __half2 h01 = __floats2half2_rn(fr[e].x, fr[e].y);
                __half2 h23 = __floats2half2_rn(fr[e].z, fr[e].w);
                uint2 v = make_uint2(*(uint32_t*)&h01, *(uint32_t*)&h23);
                *(uint2*)((char*)smem + (s ^ 1) * N0_STAGE + adst[e]) = v;
                *(uint2*)pO[e] = v;  pO[e] += A_STRIDE;
            }
        }

        // ---- compute chunk i ----
#pragma unroll
        for (int kk = 0; kk < 4; ++kk) {
            const uint32_t ko = (uint32_t)(kk * 32);
            uint32_t a0[4], a1[4];
            ldsm_x4(a0, stg + aoff0 + ko);
            ldsm_x4(a1, stg + aoff1 + ko);
            uint32_t bb[8][2];
#pragma unroll
            for (int p = 0; p < 4; ++p) {
                uint32_t r[4];
                ldsm_x4(r, stg + boff[p] + ko);
                bb[2 * p][0]     = r[0];
                bb[2 * p + 1][0] = r[1];
                bb[2 * p][1]     = r[2];
                bb[2 * p + 1][1] = r[3];
            }
#pragma unroll
            for (int nt = 0; nt < 8; ++nt) {
                mma_f16(d[0][nt], a0, bb[nt]);
                mma_f16(d[1][nt], a1, bb[nt]);
            }
        }
    }

    // ---- epilogue ----
#pragma unroll
    for (int mt = 0; mt < 2; ++mt) {
        float s0 = 0.f, s1 = 0.f;
#pragma unroll
        for (int nt = 0; nt < 8; ++nt) {
            int c0 = wn * 64 + nt * 8 + (lane & 3) * 2;
            float h0 = Hs[c0], v0 = Vs[c0];
            float h1 = Hs[c0 + 1], v1 = Vs[c0 + 1];
            s0 += fast_tanh(d[mt][nt][0] + h0) * v0 + fast_tanh(d[mt][nt][1] + h1) * v1;
            s1 += fast_tanh(d[mt][nt][2] + h0) * v0 + fast_tanh(d[mt][nt][3] + h1) * v1;
        }
#pragma unroll
        for (int o = 1; o <= 2; o <<= 1) {
            s0 += __shfl_xor_sync(~0u, s0, o);
            s1 += __shfl_xor_sync(~0u, s1, o);
        }
        if ((lane & 3) == 0) {
            int r = wm * 32 + mt * 16 + (lane >> 2);
            partS[wn * 128 + r]     = s0;
            partS[wn * 128 + r + 8] = s1;
        }
    }
    __syncthreads();
    if (tid < 128)
        g_scorep[m0 + tid] = partS[tid] + partS[128 + tid];
}

// ===========================================================================
// Kernel C1: nc=1..3 — R8 kernel verbatim, reads g_F16, 3-stage pipeline.
// ===========================================================================
static constexpr int R_STAGE = 2 * TILE;             // 36864
static constexpr int R_NSTG  = 3;
static constexpr int R_OFF_A = 0;
static constexpr int R_OFF_B = TILE;
static constexpr int R_PART  = R_NSTG * R_STAGE;     // 110592
static constexpr int R_H     = R_PART + 1024;
static constexpr int R_V     = R_H + 512;
static constexpr int R_SMEM  = R_V + 512;            // 112640

__global__ __launch_bounds__(256, 2) void score_mma_rest(const float* __restrict__ V)
{
    extern __shared__ char smem[];
    const uint32_t sb = smem_u32(smem);
    const int tid  = threadIdx.x;
    const int lane = tid & 31;
    const int wid  = tid >> 5;
    const int wm   = wid & 3;
    const int wn   = wid >> 2;
    const int nc   = blockIdx.x + 1;     // 1..3
    const int mb   = blockIdx.y;
    const int m0   = mb * 128;
    const int b    = mb >> 3;

    float* partS = (float*)(smem + R_PART);
    float* Hs    = (float*)(smem + R_H);
    float* Vs    = (float*)(smem + R_V);
    if (tid < 128) {
        Hs[tid] = g_H[b * ATT_ + nc * 128 + tid];
        Vs[tid] = V[nc * 128 + tid];
    }

    float d[2][8][4];
#pragma unroll
    for (int mt = 0; mt < 2; ++mt)
#pragma unroll
        for (int nt = 0; nt < 8; ++nt)
#pragma unroll
            for (int e = 0; e < 4; ++e) d[mt][nt][e] = 0.f;

    uint32_t dsto[4];
    const __half* pA[4];
    const __half* pB[4];
#pragma unroll
    for (int e = 0; e < 4; ++e) {
        int j = tid + e * 256, row = j >> 3, q = j & 7;
        dsto[e] = (uint32_t)(row * PITCH + q * 16);
        pA[e] = g_F16 + (((size_t)(mb * 32) * 128 + row) << 6) + q * 8;
        pB[e] = g_B16 + (((size_t)(nc * 128 + row)) << 6) + q * 8;
    }

#pragma unroll
    for (int c = 0; c < 2; ++c) {
        const uint32_t stg = sb + c * R_STAGE;
#pragma unroll
        for (int e = 0; e < 4; ++e) {
            cp16(stg + R_OFF_A + dsto[e], pA[e]);
            cp16(stg + R_OFF_B + dsto[e], pB[e]);
            pA[e] += A_STRIDE;
            pB[e] += B_STRIDE;
        }
        cp_commit();
    }

    const uint32_t aoff0 = R_OFF_A + (uint32_t)(wm * 32 + (lane & 15)) * PITCH +
                           (uint32_t)(((lane >> 4) & 1) * 16);
    const uint32_t aoff1 = aoff0 + 16 * PITCH;
    uint32_t boff[4];
#pragma unroll
    for (int p = 0; p < 4; ++p)
        boff[p] = R_OFF_B + (uint32_t)(wn * 64 + p * 16 + (lane & 15)) * PITCH +
                  (uint32_t)(((lane >> 4) & 1) * 16);

    int cs = 0, ps = 2;
#pragma unroll 1
    for (int i = 0; i < NCHUNK; ++i) {
        const uint32_t stg = sb + cs * R_STAGE;
        if (++cs == R_NSTG) cs = 0;

        cp_wait1();
        __syncthreads();

        if (i + 2 < NCHUNK) {
            const uint32_t nstg = sb + ps * R_STAGE;
            if (++ps == R_NSTG) ps = 0;
#pragma unroll
            for (int e = 0; e < 4; ++e) {
                cp16(nstg + R_OFF_A + dsto[e], pA[e]);
                cp16(nstg + R_OFF_B + dsto[e], pB[e]);
                pA[e] += A_STRIDE;
                pB[e] += B_STRIDE;
            }
            cp_commit();
        }

#pragma unroll
        for (int kk = 0; kk < 4; ++kk) {
            const uint32_t ko = (uint32_t)(kk * 32);
            uint32_t a0[4], a1[4];
            ldsm_x4(a0, stg + aoff0 + ko);
            ldsm_x4(a1, stg + aoff1 + ko);
            uint32_t bb[8][2];
#pragma unroll
            for (int p = 0; p < 4; ++p) {
                uint32_t r[4];
                ldsm_x4(r, stg + boff[p] + ko);
                bb[2 * p][0]     = r[0];
                bb[2 * p + 1][0] = r[1];
                bb[2 * p][1]     = r[2];
                bb[2 * p + 1][1] = r[3];
            }
#pragma unroll
            for (int nt = 0; nt < 8; ++nt) {
                mma_f16(d[0][nt], a0, bb[nt]);
                mma_f16(d[1][nt], a1, bb[nt]);
            }
        }
    }

#pragma unroll
    for (int mt = 0; mt < 2; ++mt) {
        float s0 = 0.f, s1 = 0.f;
#pragma unroll
        for (int nt = 0; nt < 8; ++nt) {
            int c0 = wn * 64 + nt * 8 + (lane & 3) * 2;
            float h0 = Hs[c0], v0 = Vs[c0];
            float h1 = Hs[c0 + 1], v1 = Vs[c0 + 1];
            s0 += fast_tanh(d[mt][nt][0] + h0) * v0 + fast_tanh(d[mt][nt][1] + h1) * v1;
            s1 += fast_tanh(d[mt][nt][2] + h0) * v0 + fast_tanh(d[mt][nt][3] + h1) * v1;
        }
#pragma unroll
        for (int o = 1; o <= 2; o <<= 1) {
            s0 += __shfl_xor_sync(~0u, s0, o);
            s1 += __shfl_xor_sync(~0u, s1, o);
        }
        if ((lane & 3) == 0) {
            int r = wm * 32 + mt * 16 + (lane >> 2);
            partS[wn * 128 + r]     = s0;
            partS[wn * 128 + r + 8] = s1;
        }
    }
    __syncthreads();
    if (tid < 128)
        g_scorep[nc * BL_ + m0 + tid] = partS[tid] + partS[128 + tid];
}

// ---------------------------------------------------------------------------
// Kernel D: combine partials + softmax over L per batch
// ---------------------------------------------------------------------------
__global__ void softmax_kernel(const float* __restrict__ bv, float* __restrict__ w) {
    __shared__ float redm[32];
    __shared__ float reds[32];
    const int b = blockIdx.x, t = threadIdx.x;
    const int idx = b * L_ + t;
    float s = g_scorep[idx] + g_scorep[BL_ + idx] + g_scorep[2 * BL_ + idx] +
              g_scorep[3 * BL_ + idx] + bv[0];
    float m = s;
#pragma unroll
    for (int o = 16; o > 0; o >>= 1) m = fmaxf(m, __shfl_xor_sync(~0u, m, o));
    if ((t & 31) == 0) redm[t >> 5] = m;
    __syncthreads();
    if (t < 32) {
        float v = redm[t];
#pragma unroll
        for (int o = 16; o > 0; o >>= 1) v = fmaxf(v, __shfl_xor_sync(~0u, v, o));
        redm[t] = v;
    }
    __syncthreads();
    m = redm[0];
    const float e = expf(s - m);
    float sum = e;
#pragma unroll
    for (int o = 16; o > 0; o >>= 1) sum += __shfl_xor_sync(~0u, sum, o);
    if ((t & 31) == 0) reds[t >> 5] = sum;
    __syncthreads();
    if (t < 32) {
        float v = reds[t];
#pragma unroll
        for (int o = 16; o > 0; o >>= 1) v += __shfl_xor_sync(~0u, v, o);
        reds[t] = v;
    }
    __syncthreads();
    w[idx] = e / reds[0];
}

// ---------------------------------------------------------------------------
// Kernel E/F: context = sum_l w*F  (fp16 tiled F; 8 L-partials, then reduced)
// ---------------------------------------------------------------------------
__global__ void context_part_kernel(const float* __restrict__ w) {
    __shared__ float ws[128];
    const int b = blockIdx.y, z = blockIdx.z, t = threadIdx.x;
    ws[t] = w[b * L_ + z * 128 + t];
    __syncthreads();
    const int e0 = blockIdx.x * 512 + t * 4;
    const int mb = b * 8 + z;
    const int c  = e0 >> 6, kk = e0 & 63;
    const __half* base = g_F16 + (((size_t)(mb * 32 + c) * 128) << 6) + kk;
    float4 acc = make_float4(0.f, 0.f, 0.f, 0.f);
#pragma unroll 4
    for (int l = 0; l < 128; ++l) {
        uint2 v = *(const uint2*)(base + ((size_t)l << 6));
        float2 f01 = __half22float2(*(const __half2*)&v.x);
        float2 f23 = __half22float2(*(const __half2*)&v.y);
        const float wl = ws[l];
        acc.x += wl * f01.x; acc.y += wl * f01.y;
        acc.z += wl * f23.x; acc.w += wl * f23.y;
    }
    *(float4*)&g_ctxp[(size_t)(z * B_ + b) * ENC_ + e0] = acc;
}

__global__ void context_reduce_kernel(float* __restrict__ ctx) {
    const int i = (blockIdx.x * 256 + threadIdx.x) * 4;
    float4 acc = make_float4(0.f, 0.f, 0.f, 0.f);
#pragma unroll
    for (int p = 0; p < 8; ++p) {
        float4 a = *(const float4*)&g_ctxp[(size_t)p * B_ * ENC_ + i];
        acc.x += a.x; acc.y += a.y; acc.z += a.z; acc.w += a.w;
    }
    *(float4*)&ctx[i] = acc;
}

// ---------------------------------------------------------------------------
// Launch
// ---------------------------------------------------------------------------
extern "C" void kernel_launch(void* const* d_in, const int* in_sizes, int n_in,
                              void* d_out, int out_size) {
    const float* F   = (const float*)d_in[0];
    const float* hid = (const float*)d_in[1];
    const float* W1  = (const float*)d_in[2];
    const float* b1  = (const float*)d_in[3];
    const float* W2  = (const float*)d_in[4];
    const float* b2  = (const float*)d_in[5];
    const float* V   = (const float*)d_in[6];
    const float* bv  = (const float*)d_in[7];

    float* out = (float*)d_out;
    float* ctx = out;
    float* wts = out + B_ * ENC_;

    cudaFuncSetAttribute(score_mma_nc0,
                         cudaFuncAttributeMaxDynamicSharedMemorySize, N0_SMEM);
    cudaFuncSetAttribute(score_mma_rest,
                         cudaFuncAttributeMaxDynamicSharedMemorySize, R_SMEM);

    proj_h_kernel<<<B_, ATT_>>>(hid, W2, b2, b1);
    prep_B_kernel<<<(ENC_ * ATT_) / 256, 256>>>(W1);
    score_mma_nc0<<<BL_ / 128, 256, N0_SMEM>>>(F, V);       // converts F -> g_F16
    score_mma_rest<<<dim3(3, BL_ / 128), 256, R_SMEM>>>(V); // reads g_F16
    softmax_kernel<<<B_, L_>>>(bv, wts);
    context_part_kernel<<<dim3(ENC_ / 512, B_, 8), 128>>>(wts);
    context_reduce_kernel<<<(B_ * ENC_) / 1024, 256>>>(ctx);
}